// round 2
// baseline (speedup 1.0000x reference)
#include <cuda_runtime.h>
#include <math.h>

// ---------------------------------------------------------------------------
// Model1_11596411699487: 5x 4D conv (valid, stride 1) + ReLU, flatten,
// dense 1280->33 + ReLU, dense 33->2, softmax.
//
// Round 2: packed fma.rn.f32x2 over the z dimension (2 MACs/instr),
// co-group splitting on the late (warp-starved) layers.
// ---------------------------------------------------------------------------

#define BATCH 256

__device__ float g_h1[BATCH * 3 * 15 * 15 * 15 * 15];
__device__ float g_h2[BATCH * 3 * 12 * 12 * 12 * 12];
__device__ float g_h3[BATCH * 4 * 9 * 9 * 9 * 9];
__device__ float g_h4[BATCH * 5 * 6 * 6 * 6 * 6];
__device__ float g_h5[BATCH * 5 * 4 * 4 * 4 * 4];

typedef unsigned long long u64;

__device__ __forceinline__ u64 pack2(float lo, float hi) {
    u64 r;
    asm("mov.b64 %0, {%1, %2};" : "=l"(r) : "f"(lo), "f"(hi));
    return r;
}
__device__ __forceinline__ void fma2(u64& d, u64 a, u64 b) {
    asm("fma.rn.f32x2 %0, %1, %2, %0;" : "+l"(d) : "l"(a), "l"(b));
}
__device__ __forceinline__ void unpack2(u64 v, float& lo, float& hi) {
    asm("mov.b64 {%0, %1}, %2;" : "=f"(lo), "=f"(hi) : "l"(v));
}

// ---------------------------------------------------------------------------
// Direct 4D conv + ReLU, z-dimension packed into f32x2 pairs.
// Thread owns one (co_group, b, w, x, y): computes Sout z-outputs for the
// CPG=ceil(Cout/COG) channels of its group, all in packed registers.
// ---------------------------------------------------------------------------
template <int Cin, int Cout, int Sin, int K, int COG>
__global__ void __launch_bounds__(128)
conv4d_relu_f32x2_kernel(const float* __restrict__ in,
                         const float* __restrict__ wt,
                         const float* __restrict__ bias,
                         float* __restrict__ out)
{
    constexpr int Sout = Sin - K + 1;
    constexpr int NP   = (Sout + 1) / 2;          // z-pairs per channel
    constexpr int CPG  = (Cout + COG - 1) / COG;  // channels per group
    constexpr int WSZ  = Cout * Cin * K * K * K * K;
    constexpr int NPOS = Sout * Sout * Sout;

    __shared__ float sw[WSZ];
    __shared__ float sb[Cout];
    for (int i = threadIdx.x; i < WSZ; i += blockDim.x) sw[i] = wt[i];
    if (threadIdx.x < Cout) sb[threadIdx.x] = bias[threadIdx.x];
    __syncthreads();

    int tid = blockIdx.x * blockDim.x + threadIdx.x;
    if (tid >= BATCH * NPOS * COG) return;

    int y0 = tid % Sout;
    int t1 = tid / Sout;
    int x0 = t1 % Sout;
    int t2 = t1 / Sout;
    int w0 = t2 % Sout;
    int t3 = t2 / Sout;
    int b  = t3 % BATCH;
    int g  = t3 / BATCH;          // co group index
    int co0 = g * CPG;

    u64 accp[CPG * NP];
#pragma unroll
    for (int c = 0; c < CPG; c++) {
        float bv = (co0 + c < Cout) ? sb[co0 + c] : 0.0f;
        u64 bp = pack2(bv, bv);
#pragma unroll
        for (int p = 0; p < NP; p++) accp[c * NP + p] = bp;
    }

    for (int ci = 0; ci < Cin; ci++) {
#pragma unroll 1
        for (int kw = 0; kw < K; kw++) {
#pragma unroll 1
            for (int kx = 0; kx < K; kx++) {
#pragma unroll
                for (int ky = 0; ky < K; ky++) {
                    const float* p = in +
                        ((((b * Cin + ci) * Sin + (w0 + kw)) * Sin + (x0 + kx)) * Sin
                         + (y0 + ky)) * Sin;
                    float r[Sin + 1];
#pragma unroll
                    for (int z = 0; z < Sin; z++) r[z] = p[z];
                    r[Sin] = 0.0f;  // pad for odd-Sout tail pair

                    // adjacent-pair views of the input row
                    u64 rp[Sin];
#pragma unroll
                    for (int i = 0; i < Sin; i++) rp[i] = pack2(r[i], r[i + 1]);

#pragma unroll
                    for (int c = 0; c < CPG; c++) {
                        int co = co0 + c;
                        if (co >= Cout) break;
#pragma unroll
                        for (int kz = 0; kz < K; kz++) {
                            float wv = sw[((((co * Cin + ci) * K + kw) * K + kx) * K + ky) * K + kz];
                            u64 w2 = pack2(wv, wv);
#pragma unroll
                            for (int pz = 0; pz < NP; pz++)
                                fma2(accp[c * NP + pz], rp[2 * pz + kz], w2);
                        }
                    }
                }
            }
        }
    }

#pragma unroll
    for (int c = 0; c < CPG; c++) {
        int co = co0 + c;
        if (co >= Cout) break;
        float* op = out +
            ((((b * Cout + co) * Sout + w0) * Sout + x0) * Sout + y0) * Sout;
#pragma unroll
        for (int pz = 0; pz < NP; pz++) {
            float lo, hi;
            unpack2(accp[c * NP + pz], lo, hi);
            int z = 2 * pz;
            op[z] = fmaxf(lo, 0.0f);
            if (z + 1 < Sout) op[z + 1] = fmaxf(hi, 0.0f);
        }
    }
}

// ---------------------------------------------------------------------------
// Head: per-sample block. dense 1280->33 (ReLU), dense 33->2, softmax.
// ---------------------------------------------------------------------------
__global__ void __launch_bounds__(64)
head_kernel(const float* __restrict__ h,
            const float* __restrict__ dw1, const float* __restrict__ db1,
            const float* __restrict__ dw2, const float* __restrict__ db2,
            float* __restrict__ out)
{
    int b = blockIdx.x;
    __shared__ float sh[1280];
    __shared__ float s1[33];

    for (int i = threadIdx.x; i < 1280; i += blockDim.x)
        sh[i] = h[b * 1280 + i];
    __syncthreads();

    int j = threadIdx.x;
    if (j < 33) {
        float s = db1[j];
        const float* wr = dw1 + j * 1280;
#pragma unroll 4
        for (int i = 0; i < 1280; i++) s += wr[i] * sh[i];
        s1[j] = fmaxf(s, 0.0f);
    }
    __syncthreads();

    if (threadIdx.x == 0) {
        float l0 = db2[0], l1 = db2[1];
        for (int jj = 0; jj < 33; jj++) {
            l0 += dw2[jj] * s1[jj];
            l1 += dw2[33 + jj] * s1[jj];
        }
        float m  = fmaxf(l0, l1);
        float e0 = expf(l0 - m);
        float e1 = expf(l1 - m);
        float inv = 1.0f / (e0 + e1);
        out[b * 2 + 0] = e0 * inv;
        out[b * 2 + 1] = e1 * inv;
    }
}

static inline int cdiv(int a, int b) { return (a + b - 1) / b; }

extern "C" void kernel_launch(void* const* d_in, const int* in_sizes, int n_in,
                              void* d_out, int out_size)
{
    const float* x   = (const float*)d_in[0];
    const float* w1  = (const float*)d_in[1];
    const float* b1  = (const float*)d_in[2];
    const float* w2  = (const float*)d_in[3];
    const float* b2  = (const float*)d_in[4];
    const float* w3  = (const float*)d_in[5];
    const float* b3  = (const float*)d_in[6];
    const float* w4  = (const float*)d_in[7];
    const float* b4  = (const float*)d_in[8];
    const float* w5  = (const float*)d_in[9];
    const float* b5  = (const float*)d_in[10];
    const float* dw1 = (const float*)d_in[11];
    const float* db1 = (const float*)d_in[12];
    const float* dw2 = (const float*)d_in[13];
    const float* db2 = (const float*)d_in[14];
    float* out = (float*)d_out;

    float *h1, *h2, *h3, *h4, *h5;
    cudaGetSymbolAddress((void**)&h1, g_h1);
    cudaGetSymbolAddress((void**)&h2, g_h2);
    cudaGetSymbolAddress((void**)&h3, g_h3);
    cudaGetSymbolAddress((void**)&h4, g_h4);
    cudaGetSymbolAddress((void**)&h5, g_h5);

    const int T = 128;

    // conv1: 1->3, 18->15, k=4
    conv4d_relu_f32x2_kernel<1, 3, 18, 4, 1>
        <<<cdiv(BATCH * 15 * 15 * 15 * 1, T), T>>>(x, w1, b1, h1);
    // conv2: 3->3, 15->12, k=4
    conv4d_relu_f32x2_kernel<3, 3, 15, 4, 1>
        <<<cdiv(BATCH * 12 * 12 * 12 * 1, T), T>>>(h1, w2, b2, h2);
    // conv3: 3->4, 12->9, k=4
    conv4d_relu_f32x2_kernel<3, 4, 12, 4, 1>
        <<<cdiv(BATCH * 9 * 9 * 9 * 1, T), T>>>(h2, w3, b3, h3);
    // conv4: 4->5, 9->6, k=4  (co split in 2 groups for occupancy)
    conv4d_relu_f32x2_kernel<4, 5, 9, 4, 2>
        <<<cdiv(BATCH * 6 * 6 * 6 * 2, T), T>>>(h3, w4, b4, h4);
    // conv5: 5->5, 6->4, k=3  (one co per thread for occupancy)
    conv4d_relu_f32x2_kernel<5, 5, 6, 3, 5>
        <<<cdiv(BATCH * 4 * 4 * 4 * 5, T), T>>>(h4, w5, b5, h5);
    // head
    head_kernel<<<BATCH, 64>>>(h5, dw1, db1, dw2, db2, out);
}

// round 3
// speedup vs baseline: 1.2729x; 1.2729x over previous
#include <cuda_runtime.h>
#include <math.h>

// ---------------------------------------------------------------------------
// Model1_11596411699487: 5x 4D conv (valid, stride 1) + ReLU, flatten,
// dense 1280->33 + ReLU, dense 33->2, softmax.
//
// Round 3: scalar FFMA (f32x2 reverted), all-K-rows batched loads per
// (ci,kw,kx) for MLP, float2 row loads where aligned, COG splits on tail.
// ---------------------------------------------------------------------------

#define BATCH 256

__device__ float g_h1[BATCH * 3 * 15 * 15 * 15 * 15];
__device__ float g_h2[BATCH * 3 * 12 * 12 * 12 * 12];
__device__ float g_h3[BATCH * 4 * 9 * 9 * 9 * 9];
__device__ float g_h4[BATCH * 5 * 6 * 6 * 6 * 6];
__device__ float g_h5[BATCH * 5 * 4 * 4 * 4 * 4];

// ---------------------------------------------------------------------------
// Direct 4D conv + ReLU.
// Thread owns (co_group, b, w, x, y); computes Sout z outputs for its CPG
// channels. Per (ci,kw,kx): batch-load ALL K ky-rows (K*Sin floats, high MLP),
// then run the dense FFMA block (Cout*K*K*Sout FFMAs) against them.
// ---------------------------------------------------------------------------
template <int Cin, int Cout, int Sin, int K, int COG>
__global__ void __launch_bounds__(128)
conv4d_relu_kernel(const float* __restrict__ in,
                   const float* __restrict__ wt,
                   const float* __restrict__ bias,
                   float* __restrict__ out)
{
    constexpr int Sout = Sin - K + 1;
    constexpr int CPG  = (Cout + COG - 1) / COG;
    constexpr int WSZ  = Cout * Cin * K * K * K * K;
    constexpr int NPOS = Sout * Sout * Sout;

    __shared__ float sw[WSZ];
    __shared__ float sb[Cout];
    for (int i = threadIdx.x; i < WSZ; i += blockDim.x) sw[i] = wt[i];
    if (threadIdx.x < Cout) sb[threadIdx.x] = bias[threadIdx.x];
    __syncthreads();

    int tid = blockIdx.x * blockDim.x + threadIdx.x;
    if (tid >= BATCH * NPOS * COG) return;

    int y0 = tid % Sout;
    int t1 = tid / Sout;
    int x0 = t1 % Sout;
    int t2 = t1 / Sout;
    int w0 = t2 % Sout;
    int t3 = t2 / Sout;
    int b  = t3 % BATCH;
    int g  = t3 / BATCH;
    int co0 = g * CPG;

    float acc[CPG * Sout];
#pragma unroll
    for (int c = 0; c < CPG; c++) {
        float bv = (co0 + c < Cout) ? sb[co0 + c] : 0.0f;
#pragma unroll
        for (int z = 0; z < Sout; z++) acc[c * Sout + z] = bv;
    }

#pragma unroll 1
    for (int ci = 0; ci < Cin; ci++) {
#pragma unroll 1
        for (int kw = 0; kw < K; kw++) {
#pragma unroll 1
            for (int kx = 0; kx < K; kx++) {
                // Batch-load all K rows for this (ci,kw,kx): high MLP.
                float r[K][Sin];
                const float* base = in +
                    ((((b * Cin + ci) * Sin + (w0 + kw)) * Sin + (x0 + kx)) * Sin
                     + y0) * Sin;
                if ((Sin & 1) == 0) {
                    // Row start index is Sin*integer -> 8B aligned when Sin even.
#pragma unroll
                    for (int ky = 0; ky < K; ky++) {
                        const float2* p2 = (const float2*)(base + ky * Sin);
#pragma unroll
                        for (int h = 0; h < Sin / 2; h++) {
                            float2 v = p2[h];
                            r[ky][2 * h]     = v.x;
                            r[ky][2 * h + 1] = v.y;
                        }
                    }
                } else {
#pragma unroll
                    for (int ky = 0; ky < K; ky++) {
                        const float* p = base + ky * Sin;
#pragma unroll
                        for (int z = 0; z < Sin; z++) r[ky][z] = p[z];
                    }
                }

#pragma unroll
                for (int ky = 0; ky < K; ky++) {
#pragma unroll
                    for (int c = 0; c < CPG; c++) {
                        int co = co0 + c;
                        if (co >= Cout) break;
#pragma unroll
                        for (int kz = 0; kz < K; kz++) {
                            float wv = sw[((((co * Cin + ci) * K + kw) * K + kx) * K + ky) * K + kz];
#pragma unroll
                            for (int z = 0; z < Sout; z++)
                                acc[c * Sout + z] += r[ky][z + kz] * wv;
                        }
                    }
                }
            }
        }
    }

#pragma unroll
    for (int c = 0; c < CPG; c++) {
        int co = co0 + c;
        if (co >= Cout) break;
        float* op = out +
            ((((b * Cout + co) * Sout + w0) * Sout + x0) * Sout + y0) * Sout;
#pragma unroll
        for (int z = 0; z < Sout; z++)
            op[z] = fmaxf(acc[c * Sout + z], 0.0f);
    }
}

// ---------------------------------------------------------------------------
// Head: per-sample block. dense 1280->33 (ReLU), dense 33->2, softmax.
// ---------------------------------------------------------------------------
__global__ void __launch_bounds__(64)
head_kernel(const float* __restrict__ h,
            const float* __restrict__ dw1, const float* __restrict__ db1,
            const float* __restrict__ dw2, const float* __restrict__ db2,
            float* __restrict__ out)
{
    int b = blockIdx.x;
    __shared__ float sh[1280];
    __shared__ float s1[33];

    for (int i = threadIdx.x; i < 1280; i += blockDim.x)
        sh[i] = h[b * 1280 + i];
    __syncthreads();

    int j = threadIdx.x;
    if (j < 33) {
        float s = db1[j];
        const float* wr = dw1 + j * 1280;
#pragma unroll 4
        for (int i = 0; i < 1280; i++) s += wr[i] * sh[i];
        s1[j] = fmaxf(s, 0.0f);
    }
    __syncthreads();

    if (threadIdx.x == 0) {
        float l0 = db2[0], l1 = db2[1];
        for (int jj = 0; jj < 33; jj++) {
            l0 += dw2[jj] * s1[jj];
            l1 += dw2[33 + jj] * s1[jj];
        }
        float m  = fmaxf(l0, l1);
        float e0 = expf(l0 - m);
        float e1 = expf(l1 - m);
        float inv = 1.0f / (e0 + e1);
        out[b * 2 + 0] = e0 * inv;
        out[b * 2 + 1] = e1 * inv;
    }
}

static inline int cdiv(int a, int b) { return (a + b - 1) / b; }

extern "C" void kernel_launch(void* const* d_in, const int* in_sizes, int n_in,
                              void* d_out, int out_size)
{
    const float* x   = (const float*)d_in[0];
    const float* w1  = (const float*)d_in[1];
    const float* b1  = (const float*)d_in[2];
    const float* w2  = (const float*)d_in[3];
    const float* b2  = (const float*)d_in[4];
    const float* w3  = (const float*)d_in[5];
    const float* b3  = (const float*)d_in[6];
    const float* w4  = (const float*)d_in[7];
    const float* b4  = (const float*)d_in[8];
    const float* w5  = (const float*)d_in[9];
    const float* b5  = (const float*)d_in[10];
    const float* dw1 = (const float*)d_in[11];
    const float* db1 = (const float*)d_in[12];
    const float* dw2 = (const float*)d_in[13];
    const float* db2 = (const float*)d_in[14];
    float* out = (float*)d_out;

    float *h1, *h2, *h3, *h4, *h5;
    cudaGetSymbolAddress((void**)&h1, g_h1);
    cudaGetSymbolAddress((void**)&h2, g_h2);
    cudaGetSymbolAddress((void**)&h3, g_h3);
    cudaGetSymbolAddress((void**)&h4, g_h4);
    cudaGetSymbolAddress((void**)&h5, g_h5);

    const int T = 128;

    // conv1: 1->3, 18->15, k=4
    conv4d_relu_kernel<1, 3, 18, 4, 1>
        <<<cdiv(BATCH * 15 * 15 * 15 * 1, T), T>>>(x, w1, b1, h1);
    // conv2: 3->3, 15->12, k=4
    conv4d_relu_kernel<3, 3, 15, 4, 1>
        <<<cdiv(BATCH * 12 * 12 * 12 * 1, T), T>>>(h1, w2, b2, h2);
    // conv3: 3->4, 12->9, k=4
    conv4d_relu_kernel<3, 4, 12, 4, 1>
        <<<cdiv(BATCH * 9 * 9 * 9 * 1, T), T>>>(h2, w3, b3, h3);
    // conv4: 4->5, 9->6, k=4  (co split x2 for occupancy)
    conv4d_relu_kernel<4, 5, 9, 4, 2>
        <<<cdiv(BATCH * 6 * 6 * 6 * 2, T), T>>>(h3, w4, b4, h4);
    // conv5: 5->5, 6->4, k=3  (co split x5 for occupancy)
    conv4d_relu_kernel<5, 5, 6, 3, 5>
        <<<cdiv(BATCH * 4 * 4 * 4 * 5, T), T>>>(h4, w5, b5, h5);
    // head
    head_kernel<<<BATCH, 64>>>(h5, dw1, db1, dw2, db2, out);
}